// round 11
// baseline (speedup 1.0000x reference)
#include <cuda_runtime.h>
#include <cstdint>

#define NN 100000
#define NB 391          // ceil(NN/256)
#define MAXE 1200000
#define MAXM 200000

// ---------------- static scratch (no allocs allowed) ----------------
__device__ float d_bufA[NN * 64];
__device__ float d_bufB[NN * 128];
__device__ float d_bufC[NN * 64];
__device__ float d_bufD[NN * 64];
__device__ int   d_degb[NN];
__device__ int   d_degm[NN];
__device__ float d_dinvb[NN];
__device__ float d_dinvm[NN];
__device__ int   d_is64;
__device__ int   d_bsb[NB], d_bsm[NB];
__device__ int   d_bob[NB], d_bom[NB];
__device__ int   d_rowb[NN], d_rowm[NN];
__device__ int   d_curb[NN], d_curm[NN];
__device__ int2  d_csrb[MAXE];
__device__ int2  d_csrm[MAXM];

// ---------------- prep: deg=1 + dtype detect ----------------
__global__ void prep_kernel(const void* __restrict__ ei, int* __restrict__ degb,
                            int* __restrict__ degm, int n) {
    int i = blockIdx.x * blockDim.x + threadIdx.x;
    if (i < n) { degb[i] = 1; degm[i] = 1; }
    if (i == 0) {
        const int* w = (const int*)ei;
        int ok = 1;
        for (int j = 0; j < 64; j++)
            if (w[2 * j + 1] != 0) ok = 0;
        d_is64 = ok;
    }
}

__device__ __forceinline__ int load_dst(const void* ei, long i, long nE) {
    if (d_is64) return (int)((const long long*)ei)[nE + i];
    return ((const int*)ei)[nE + i];
}
__device__ __forceinline__ int2 load_edge(const void* ei, long e, long nE) {
    if (d_is64) {
        const long long* p = (const long long*)ei;
        return make_int2((int)p[e], (int)p[nE + e]);
    }
    const int* p = (const int*)ei;
    return make_int2(p[e], p[nE + e]);
}

__global__ void count_both_kernel(const void* __restrict__ ei, long nE, int* __restrict__ degb,
                                  const void* __restrict__ mei, long nM, int* __restrict__ degm) {
    long i = blockIdx.x * (long)blockDim.x + threadIdx.x;
    if (i < nE) {
        atomicAdd(&degb[load_dst(ei, i, nE)], 1);
    } else if (i < nE + nM) {
        atomicAdd(&degm[load_dst(mei, i - nE, nM)], 1);
    }
}

// ---------------- scan step 1: dinv + per-block sums ----------------
__global__ void dinv_s1_kernel(const int* __restrict__ degb, const int* __restrict__ degm,
                               float* __restrict__ dinvb, float* __restrict__ dinvm, int n) {
    __shared__ int sh[256];
    int b = blockIdx.x;
    bool meta = b >= NB;
    int lb = meta ? b - NB : b;
    const int* deg = meta ? degm : degb;
    float* dinv = meta ? dinvm : dinvb;
    int* bs = meta ? d_bsm : d_bsb;
    int i = lb * 256 + threadIdx.x;
    int val = 0;
    if (i < n) { int dg = deg[i]; dinv[i] = rsqrtf((float)dg); val = dg - 1; }
    sh[threadIdx.x] = val;
    __syncthreads();
    #pragma unroll
    for (int off = 128; off > 0; off >>= 1) {
        if (threadIdx.x < off) sh[threadIdx.x] += sh[threadIdx.x + off];
        __syncthreads();
    }
    if (threadIdx.x == 0) bs[lb] = sh[0];
}

__global__ void scan_bs_kernel() {
    __shared__ int sh[512];
    int t = threadIdx.x;
    sh[t] = (t < NB) ? d_bsb[t] : 0;
    __syncthreads();
    for (int off = 1; off < 512; off <<= 1) {
        int v = (t >= off) ? sh[t - off] : 0;
        __syncthreads();
        sh[t] += v;
        __syncthreads();
    }
    if (t < NB) d_bob[t] = (t == 0) ? 0 : sh[t - 1];
    __syncthreads();
    sh[t] = (t < NB) ? d_bsm[t] : 0;
    __syncthreads();
    for (int off = 1; off < 512; off <<= 1) {
        int v = (t >= off) ? sh[t - off] : 0;
        __syncthreads();
        sh[t] += v;
        __syncthreads();
    }
    if (t < NB) d_bom[t] = (t == 0) ? 0 : sh[t - 1];
}

__global__ void rowptr_kernel(const int* __restrict__ degb, const int* __restrict__ degm, int n) {
    __shared__ int sh[256];
    int b = blockIdx.x;
    bool meta = b >= NB;
    int lb = meta ? b - NB : b;
    const int* deg = meta ? degm : degb;
    int* row = meta ? d_rowm : d_rowb;
    int* cur = meta ? d_curm : d_curb;
    int boff = meta ? d_bom[lb] : d_bob[lb];
    int i = lb * 256 + threadIdx.x;
    int val = (i < n) ? deg[i] - 1 : 0;
    sh[threadIdx.x] = val;
    __syncthreads();
    for (int off = 1; off < 256; off <<= 1) {
        int v = (threadIdx.x >= off) ? sh[threadIdx.x - off] : 0;
        __syncthreads();
        sh[threadIdx.x] += v;
        __syncthreads();
    }
    if (i < n) {
        int ex = sh[threadIdx.x] - val + boff;
        row[i] = ex;
        cur[i] = ex;
    }
}

// ---------------- CSR scatter ----------------
__global__ void scatter_both_kernel(const void* __restrict__ ei, long nE, const float* __restrict__ dinvb,
                                    const void* __restrict__ mei, long nM, const float* __restrict__ dinvm) {
    long i = blockIdx.x * (long)blockDim.x + threadIdx.x;
    if (i < nE) {
        int2 sd = load_edge(ei, i, nE);
        float nrm = dinvb[sd.x] * dinvb[sd.y];
        int pos = atomicAdd(&d_curb[sd.y], 1);
        d_csrb[pos] = make_int2(sd.x, __float_as_int(nrm));
    } else if (i < nE + nM) {
        long e = i - nE;
        int2 sd = load_edge(mei, e, nM);
        float nrm = dinvm[sd.x] * dinvm[sd.y];
        int pos = atomicAdd(&d_curm[sd.y], 1);
        d_csrm[pos] = make_int2(sd.x, __float_as_int(nrm));
    }
}

// ---------------- CSR aggregation: warp/node, self-loop+bias fused, opt. log_softmax ------
template <bool BIAS, bool SMAX>
__launch_bounds__(256) __global__
void agg_csr_kernel(const float* __restrict__ h, float* __restrict__ out,
                    const int* __restrict__ row, const int* __restrict__ deg,
                    const int2* __restrict__ csr, const float* __restrict__ bias, int n) {
    int d = blockIdx.x * (blockDim.x >> 5) + (threadIdx.x >> 5);
    if (d >= n) return;
    int lane = threadIdx.x & 31;
    int c = lane * 2;
    int dg = deg[d];
    int start = row[d];
    int m = dg - 1;
    float inv = 1.0f / (float)dg;
    float2 acc = *(const float2*)(h + (long)d * 64 + c);
    acc.x *= inv; acc.y *= inv;
    if (BIAS) {
        float2 bb = *(const float2*)(bias + c);
        acc.x += bb.x; acc.y += bb.y;
    }
    int i = 0;
    for (; i + 4 <= m; i += 4) {
        int2 e0 = csr[start + i], e1 = csr[start + i + 1];
        int2 e2 = csr[start + i + 2], e3 = csr[start + i + 3];
        float2 v0 = *(const float2*)(h + (long)e0.x * 64 + c);
        float2 v1 = *(const float2*)(h + (long)e1.x * 64 + c);
        float2 v2 = *(const float2*)(h + (long)e2.x * 64 + c);
        float2 v3 = *(const float2*)(h + (long)e3.x * 64 + c);
        float n0 = __int_as_float(e0.y), n1 = __int_as_float(e1.y);
        float n2 = __int_as_float(e2.y), n3 = __int_as_float(e3.y);
        acc.x += v0.x * n0 + v1.x * n1 + v2.x * n2 + v3.x * n3;
        acc.y += v0.y * n0 + v1.y * n1 + v2.y * n2 + v3.y * n3;
    }
    for (; i < m; i++) {
        int2 e = csr[start + i];
        float2 v = *(const float2*)(h + (long)e.x * 64 + c);
        float nr = __int_as_float(e.y);
        acc.x += v.x * nr;
        acc.y += v.y * nr;
    }
    if (SMAX) {
        float mx = fmaxf(acc.x, acc.y);
        #pragma unroll
        for (int off = 16; off > 0; off >>= 1)
            mx = fmaxf(mx, __shfl_xor_sync(0xFFFFFFFFu, mx, off));
        float s = __expf(acc.x - mx) + __expf(acc.y - mx);
        #pragma unroll
        for (int off = 16; off > 0; off >>= 1)
            s += __shfl_xor_sync(0xFFFFFFFFu, s, off);
        float l = mx + __logf(s);
        acc.x -= l; acc.y -= l;
    }
    *(float2*)(out + (long)d * 64 + c) = acc;
}

// ---------------- tf32 tensor-core GEMM (vectorized float4 prologue) ----------------
__device__ __forceinline__ uint32_t f2tf32(float v) {
    uint32_t o;
    asm("cvt.rna.tf32.f32 %0, %1;" : "=r"(o) : "f"(v));
    return o;
}
__device__ __forceinline__ float cvf(float v) { return __uint_as_float(f2tf32(v)); }
__device__ __forceinline__ void mma_tf32(float* d, const uint32_t* a, const uint32_t* b) {
    asm volatile(
        "mma.sync.aligned.m16n8k8.row.col.f32.tf32.tf32.f32 "
        "{%0,%1,%2,%3},{%4,%5,%6,%7},{%8,%9},{%0,%1,%2,%3};"
        : "+f"(d[0]), "+f"(d[1]), "+f"(d[2]), "+f"(d[3])
        : "r"(a[0]), "r"(a[1]), "r"(a[2]), "r"(a[3]), "r"(b[0]), "r"(b[1]));
}

template <int FIN, int FOUT, bool BR>
__launch_bounds__(256) __global__
void mma_gemm_kernel(const float* __restrict__ A, const float* __restrict__ W,
                     const float* __restrict__ bias, float* __restrict__ C, int N) {
    constexpr int KS = FIN / 8;
    constexpr int NC = FOUT / 8;
    constexpr int NCW = NC / 2;
    extern __shared__ float sm[];
    float* As = sm;                       // 8 mfrags * KS * 32 * 4
    float* Bs = sm + 8 * KS * 128;        // KS * NC * 32 * 2

    const int t = threadIdx.x;
    const int row0 = blockIdx.x * 128;

    // --- A tile (128 x FIN), float4 loads, fragment-permuted tf32 stores ---
    for (int idx = t; idx < 128 * (FIN / 4); idx += 256) {
        int row = idx / (FIN / 4);
        int c4 = (idx % (FIN / 4)) * 4;
        float4 v = make_float4(0.f, 0.f, 0.f, 0.f);
        if (row0 + row < N) v = *(const float4*)(A + (long)(row0 + row) * FIN + c4);
        int mf = row >> 4, r0 = row & 15;
        int ks = c4 >> 3;
        int thb = (r0 & 7) << 2;                       // th for col&3==0
        int slot = (r0 >> 3) | (((c4 & 7) >> 2) << 1); // fixed across the 4 cols
        int base = ((mf * KS + ks) * 32) * 4 + slot;
        As[base + (thb + 0) * 4] = cvf(v.x);
        As[base + (thb + 1) * 4] = cvf(v.y);
        As[base + (thb + 2) * 4] = cvf(v.z);
        As[base + (thb + 3) * 4] = cvf(v.w);
    }
    // --- W (FIN x FOUT), float4 loads over n, fragment-permuted tf32 stores ---
    for (int idx = t; idx < FIN * (FOUT / 4); idx += 256) {
        int k = idx / (FOUT / 4);
        int n4 = (idx % (FOUT / 4)) * 4;
        float4 v = *(const float4*)(W + k * FOUT + n4);
        int ks = k >> 3;
        int slot = (k & 7) >> 2;
        int bth = ((n4 & 7) << 2) | (k & 3);           // th for j==0; +4 per j
        int nc = n4 >> 3;                              // fixed (n4 aligned 4)
        int base = ((ks * NC + nc) * 32) * 2 + slot;
        Bs[base + (bth + 0) * 2] = cvf(v.x);
        Bs[base + (bth + 4) * 2] = cvf(v.y);
        Bs[base + (bth + 8) * 2] = cvf(v.z);
        Bs[base + (bth + 12) * 2] = cvf(v.w);
    }
    __syncthreads();

    const int w = t >> 5, lane = t & 31;
    const int mw = w & 3, nw = w >> 2;

    float acc[2][NCW][4];
    #pragma unroll
    for (int i = 0; i < 2; i++)
        #pragma unroll
        for (int j = 0; j < NCW; j++)
            #pragma unroll
            for (int q = 0; q < 4; q++) acc[i][j][q] = 0.f;

    #pragma unroll
    for (int ks = 0; ks < KS; ks++) {
        uint32_t a0[4], a1[4];
        *(float4*)a0 = *(const float4*)(As + ((((2 * mw + 0) * KS + ks) * 32 + lane) << 2));
        *(float4*)a1 = *(const float4*)(As + ((((2 * mw + 1) * KS + ks) * 32 + lane) << 2));
        #pragma unroll
        for (int nc = 0; nc < NCW; nc++) {
            uint32_t b[2];
            *(float2*)b = *(const float2*)(Bs + (((ks * NC + nw * NCW + nc) * 32 + lane) << 1));
            mma_tf32(acc[0][nc], a0, b);
            mma_tf32(acc[1][nc], a1, b);
        }
    }

    const int cbase = nw * (NCW * 8) + (lane & 3) * 2;
    #pragma unroll
    for (int mi = 0; mi < 2; mi++) {
        int r0r = row0 + (2 * mw + mi) * 16 + (lane >> 2);
        int r1r = r0r + 8;
        #pragma unroll
        for (int nc = 0; nc < NCW; nc++) {
            int cc = cbase + nc * 8;
            float2 lo = make_float2(acc[mi][nc][0], acc[mi][nc][1]);
            float2 hi = make_float2(acc[mi][nc][2], acc[mi][nc][3]);
            if (BR) {
                float2 bb = *(const float2*)(bias + cc);
                lo.x = fmaxf(lo.x + bb.x, 0.f); lo.y = fmaxf(lo.y + bb.y, 0.f);
                hi.x = fmaxf(hi.x + bb.x, 0.f); hi.y = fmaxf(hi.y + bb.y, 0.f);
            }
            if (r0r < N) *(float2*)(C + (long)r0r * FOUT + cc) = lo;
            if (r1r < N) *(float2*)(C + (long)r1r * FOUT + cc) = hi;
        }
    }
}

// ---------------- launch ----------------
static inline long cdiv(long a, long b) { return (a + b - 1) / b; }

extern "C" void kernel_launch(void* const* d_in, const int* in_sizes, int n_in,
                              void* d_out, int out_size) {
    const float* x = (const float*)d_in[0];
    const void* ei = d_in[1];
    const void* mei = d_in[2];
    const float* W1 = (const float*)d_in[3];
    const float* b1 = (const float*)d_in[4];
    const float* W2 = (const float*)d_in[5];
    const float* b2 = (const float*)d_in[6];
    const long nE = in_sizes[1] / 2;
    const long nM = in_sizes[2] / 2;
    const int n = in_sizes[0] / 64;
    float* out = (float*)d_out;

    float *bufA, *bufB, *bufC, *bufD, *dinvb, *dinvm;
    int *degb, *degm, *rowb, *rowm;
    int2 *csrb, *csrm;
    cudaGetSymbolAddress((void**)&bufA, d_bufA);
    cudaGetSymbolAddress((void**)&bufB, d_bufB);
    cudaGetSymbolAddress((void**)&bufC, d_bufC);
    cudaGetSymbolAddress((void**)&bufD, d_bufD);
    cudaGetSymbolAddress((void**)&degb, d_degb);
    cudaGetSymbolAddress((void**)&degm, d_degm);
    cudaGetSymbolAddress((void**)&dinvb, d_dinvb);
    cudaGetSymbolAddress((void**)&dinvm, d_dinvm);
    cudaGetSymbolAddress((void**)&rowb, d_rowb);
    cudaGetSymbolAddress((void**)&rowm, d_rowm);
    cudaGetSymbolAddress((void**)&csrb, d_csrb);
    cudaGetSymbolAddress((void**)&csrm, d_csrm);

    const int SM1 = (8 * 8 * 128 + 8 * 16 * 64) * 4;     // 64 KB
    const int SM2 = (8 * 16 * 128 + 16 * 8 * 64) * 4;    // 96 KB
    cudaFuncSetAttribute(mma_gemm_kernel<64, 128, true>,
                         cudaFuncAttributeMaxDynamicSharedMemorySize, SM1);
    cudaFuncSetAttribute(mma_gemm_kernel<128, 64, false>,
                         cudaFuncAttributeMaxDynamicSharedMemorySize, SM2);

    const long gemB = cdiv(n, 128);
    const long aggB = cdiv(n, 8);

    // ---- CSR build ----
    prep_kernel<<<cdiv(n, 256), 256>>>(ei, degb, degm, n);                           // 0
    count_both_kernel<<<cdiv(nE + nM, 256), 256>>>(ei, nE, degb, mei, nM, degm);     // 1
    dinv_s1_kernel<<<2 * NB, 256>>>(degb, degm, dinvb, dinvm, n);                    // 2
    scan_bs_kernel<<<1, 512>>>();                                                    // 3
    rowptr_kernel<<<2 * NB, 256>>>(degb, degm, n);                                   // 4
    scatter_both_kernel<<<cdiv(nE + nM, 256), 256>>>(ei, nE, dinvb, mei, nM, dinvm); // 5

    // ---- base graph: conv1 + conv2 ----
    agg_csr_kernel<false, false><<<aggB, 256>>>(x, bufA, rowb, degb, csrb, nullptr, n);   // 6
    mma_gemm_kernel<64, 128, true><<<gemB, 256, SM1>>>(bufA, W1, b1, bufB, n);            // 7
    mma_gemm_kernel<128, 64, false><<<gemB, 256, SM2>>>(bufB, W2, nullptr, bufC, n);      // 8
    agg_csr_kernel<true, false><<<aggB, 256>>>(bufC, bufD, rowb, degb, csrb, b2, n);      // 9

    // ---- meta graph: conv3 + conv4 + log_softmax ----
    agg_csr_kernel<false, false><<<aggB, 256>>>(bufD, bufA, rowm, degm, csrm, nullptr, n); // 10
    mma_gemm_kernel<64, 128, true><<<gemB, 256, SM1>>>(bufA, W1, b1, bufB, n);            // 11
    mma_gemm_kernel<128, 64, false><<<gemB, 256, SM2>>>(bufB, W2, nullptr, bufC, n);      // 12
    agg_csr_kernel<true, true><<<aggB, 256>>>(bufC, out, rowm, degm, csrm, b2, n);        // 13
}

// round 14
// speedup vs baseline: 1.2316x; 1.2316x over previous
#include <cuda_runtime.h>
#include <cstdint>

#define NN 100000
#define NB 391          // ceil(NN/256)
#define MAXE 1200000
#define MAXM 200000

// ---------------- static scratch (no allocs allowed) ----------------
__device__ float d_bufA[NN * 64];
__device__ float d_bufB[NN * 128];
__device__ float d_bufC[NN * 64];
__device__ float d_bufD[NN * 64];
__device__ int   d_degb[NN];
__device__ int   d_degm[NN];
__device__ float d_dinvb[NN];
__device__ float d_dinvm[NN];
__device__ int   d_is64;
__device__ int   d_bsb[NB], d_bsm[NB];
__device__ int   d_bob[NB], d_bom[NB];
__device__ int   d_rowb[NN], d_rowm[NN];
__device__ int   d_curb[NN], d_curm[NN];
__device__ int2  d_csrb[MAXE];
__device__ int2  d_csrm[MAXM];

// ---------------- prep: deg=1 + dtype detect ----------------
__global__ void prep_kernel(const void* __restrict__ ei, int* __restrict__ degb,
                            int* __restrict__ degm, int n) {
    int i = blockIdx.x * blockDim.x + threadIdx.x;
    if (i < n) { degb[i] = 1; degm[i] = 1; }
    if (i == 0) {
        const int* w = (const int*)ei;
        int ok = 1;
        for (int j = 0; j < 64; j++)
            if (w[2 * j + 1] != 0) ok = 0;
        d_is64 = ok;
    }
}

__device__ __forceinline__ int load_dst(const void* ei, long i, long nE) {
    if (d_is64) return (int)((const long long*)ei)[nE + i];
    return ((const int*)ei)[nE + i];
}
__device__ __forceinline__ int2 load_edge(const void* ei, long e, long nE) {
    if (d_is64) {
        const long long* p = (const long long*)ei;
        return make_int2((int)p[e], (int)p[nE + e]);
    }
    const int* p = (const int*)ei;
    return make_int2(p[e], p[nE + e]);
}

__global__ void count_both_kernel(const void* __restrict__ ei, long nE, int* __restrict__ degb,
                                  const void* __restrict__ mei, long nM, int* __restrict__ degm) {
    long i = blockIdx.x * (long)blockDim.x + threadIdx.x;
    if (i < nE) {
        atomicAdd(&degb[load_dst(ei, i, nE)], 1);
    } else if (i < nE + nM) {
        atomicAdd(&degm[load_dst(mei, i - nE, nM)], 1);
    }
}

// ---------------- scan step 1: dinv + per-block sums ----------------
__global__ void dinv_s1_kernel(const int* __restrict__ degb, const int* __restrict__ degm,
                               float* __restrict__ dinvb, float* __restrict__ dinvm, int n) {
    __shared__ int sh[256];
    int b = blockIdx.x;
    bool meta = b >= NB;
    int lb = meta ? b - NB : b;
    const int* deg = meta ? degm : degb;
    float* dinv = meta ? dinvm : dinvb;
    int* bs = meta ? d_bsm : d_bsb;
    int i = lb * 256 + threadIdx.x;
    int val = 0;
    if (i < n) { int dg = deg[i]; dinv[i] = rsqrtf((float)dg); val = dg - 1; }
    sh[threadIdx.x] = val;
    __syncthreads();
    #pragma unroll
    for (int off = 128; off > 0; off >>= 1) {
        if (threadIdx.x < off) sh[threadIdx.x] += sh[threadIdx.x + off];
        __syncthreads();
    }
    if (threadIdx.x == 0) bs[lb] = sh[0];
}

__global__ void scan_bs_kernel() {
    __shared__ int sh[512];
    int t = threadIdx.x;
    sh[t] = (t < NB) ? d_bsb[t] : 0;
    __syncthreads();
    for (int off = 1; off < 512; off <<= 1) {
        int v = (t >= off) ? sh[t - off] : 0;
        __syncthreads();
        sh[t] += v;
        __syncthreads();
    }
    if (t < NB) d_bob[t] = (t == 0) ? 0 : sh[t - 1];
    __syncthreads();
    sh[t] = (t < NB) ? d_bsm[t] : 0;
    __syncthreads();
    for (int off = 1; off < 512; off <<= 1) {
        int v = (t >= off) ? sh[t - off] : 0;
        __syncthreads();
        sh[t] += v;
        __syncthreads();
    }
    if (t < NB) d_bom[t] = (t == 0) ? 0 : sh[t - 1];
}

__global__ void rowptr_kernel(const int* __restrict__ degb, const int* __restrict__ degm, int n) {
    __shared__ int sh[256];
    int b = blockIdx.x;
    bool meta = b >= NB;
    int lb = meta ? b - NB : b;
    const int* deg = meta ? degm : degb;
    int* row = meta ? d_rowm : d_rowb;
    int* cur = meta ? d_curm : d_curb;
    int boff = meta ? d_bom[lb] : d_bob[lb];
    int i = lb * 256 + threadIdx.x;
    int val = (i < n) ? deg[i] - 1 : 0;
    sh[threadIdx.x] = val;
    __syncthreads();
    for (int off = 1; off < 256; off <<= 1) {
        int v = (threadIdx.x >= off) ? sh[threadIdx.x - off] : 0;
        __syncthreads();
        sh[threadIdx.x] += v;
        __syncthreads();
    }
    if (i < n) {
        int ex = sh[threadIdx.x] - val + boff;
        row[i] = ex;
        cur[i] = ex;
    }
}

// ---------------- CSR scatter ----------------
__global__ void scatter_both_kernel(const void* __restrict__ ei, long nE, const float* __restrict__ dinvb,
                                    const void* __restrict__ mei, long nM, const float* __restrict__ dinvm) {
    long i = blockIdx.x * (long)blockDim.x + threadIdx.x;
    if (i < nE) {
        int2 sd = load_edge(ei, i, nE);
        float nrm = dinvb[sd.x] * dinvb[sd.y];
        int pos = atomicAdd(&d_curb[sd.y], 1);
        d_csrb[pos] = make_int2(sd.x, __float_as_int(nrm));
    } else if (i < nE + nM) {
        long e = i - nE;
        int2 sd = load_edge(mei, e, nM);
        float nrm = dinvm[sd.x] * dinvm[sd.y];
        int pos = atomicAdd(&d_curm[sd.y], 1);
        d_csrm[pos] = make_int2(sd.x, __float_as_int(nrm));
    }
}

// ---------------- CSR aggregation: warp/node, self-loop+bias fused, opt. log_softmax ------
template <bool BIAS, bool SMAX>
__launch_bounds__(256) __global__
void agg_csr_kernel(const float* __restrict__ h, float* __restrict__ out,
                    const int* __restrict__ row, const int* __restrict__ deg,
                    const int2* __restrict__ csr, const float* __restrict__ bias, int n) {
    int d = blockIdx.x * (blockDim.x >> 5) + (threadIdx.x >> 5);
    if (d >= n) return;
    int lane = threadIdx.x & 31;
    int c = lane * 2;
    int dg = deg[d];
    int start = row[d];
    int m = dg - 1;
    float inv = 1.0f / (float)dg;
    float2 acc = *(const float2*)(h + (long)d * 64 + c);
    acc.x *= inv; acc.y *= inv;
    if (BIAS) {
        float2 bb = *(const float2*)(bias + c);
        acc.x += bb.x; acc.y += bb.y;
    }
    int i = 0;
    for (; i + 4 <= m; i += 4) {
        int2 e0 = csr[start + i], e1 = csr[start + i + 1];
        int2 e2 = csr[start + i + 2], e3 = csr[start + i + 3];
        float2 v0 = *(const float2*)(h + (long)e0.x * 64 + c);
        float2 v1 = *(const float2*)(h + (long)e1.x * 64 + c);
        float2 v2 = *(const float2*)(h + (long)e2.x * 64 + c);
        float2 v3 = *(const float2*)(h + (long)e3.x * 64 + c);
        float n0 = __int_as_float(e0.y), n1 = __int_as_float(e1.y);
        float n2 = __int_as_float(e2.y), n3 = __int_as_float(e3.y);
        acc.x += v0.x * n0 + v1.x * n1 + v2.x * n2 + v3.x * n3;
        acc.y += v0.y * n0 + v1.y * n1 + v2.y * n2 + v3.y * n3;
    }
    for (; i < m; i++) {
        int2 e = csr[start + i];
        float2 v = *(const float2*)(h + (long)e.x * 64 + c);
        float nr = __int_as_float(e.y);
        acc.x += v.x * nr;
        acc.y += v.y * nr;
    }
    if (SMAX) {
        float mx = fmaxf(acc.x, acc.y);
        #pragma unroll
        for (int off = 16; off > 0; off >>= 1)
            mx = fmaxf(mx, __shfl_xor_sync(0xFFFFFFFFu, mx, off));
        float s = __expf(acc.x - mx) + __expf(acc.y - mx);
        #pragma unroll
        for (int off = 16; off > 0; off >>= 1)
            s += __shfl_xor_sync(0xFFFFFFFFu, s, off);
        float l = mx + __logf(s);
        acc.x -= l; acc.y -= l;
    }
    *(float2*)(out + (long)d * 64 + c) = acc;
}

// ---------------- tf32 tensor-core GEMM (R7 scalar prologue, known-good) ----------------
__device__ __forceinline__ uint32_t f2tf32(float v) {
    uint32_t o;
    asm("cvt.rna.tf32.f32 %0, %1;" : "=r"(o) : "f"(v));
    return o;
}
__device__ __forceinline__ void mma_tf32(float* d, const uint32_t* a, const uint32_t* b) {
    asm volatile(
        "mma.sync.aligned.m16n8k8.row.col.f32.tf32.tf32.f32 "
        "{%0,%1,%2,%3},{%4,%5,%6,%7},{%8,%9},{%0,%1,%2,%3};"
        : "+f"(d[0]), "+f"(d[1]), "+f"(d[2]), "+f"(d[3])
        : "r"(a[0]), "r"(a[1]), "r"(a[2]), "r"(a[3]), "r"(b[0]), "r"(b[1]));
}

template <int FIN, int FOUT, bool BR>
__launch_bounds__(256) __global__
void mma_gemm_kernel(const float* __restrict__ A, const float* __restrict__ W,
                     const float* __restrict__ bias, float* __restrict__ C, int N) {
    constexpr int KS = FIN / 8;
    constexpr int NC = FOUT / 8;
    constexpr int NCW = NC / 2;
    extern __shared__ float sm[];
    float* As = sm;
    float* Bs = sm + 8 * KS * 128;

    const int t = threadIdx.x;
    const int row0 = blockIdx.x * 128;

    for (int idx = t; idx < 128 * FIN; idx += 256) {
        int row = idx / FIN, col = idx % FIN;
        float v = (row0 + row < N) ? A[(long)(row0 + row) * FIN + col] : 0.f;
        int mf = row >> 4, r0 = row & 15;
        int ks = col >> 3;
        int th = ((r0 & 7) << 2) | (col & 3);
        int slot = (r0 >> 3) | (((col & 7) >> 2) << 1);
        As[(((mf * KS + ks) * 32 + th) << 2) | slot] = __uint_as_float(f2tf32(v));
    }
    for (int idx = t; idx < FIN * FOUT; idx += 256) {
        int k = idx / FOUT, nn = idx % FOUT;
        float v = W[idx];
        int ks = k >> 3;
        int th = ((nn & 7) << 2) | (k & 3);
        int slot = (k & 7) >> 2;
        int nc = nn >> 3;
        Bs[(((ks * NC + nc) * 32 + th) << 1) | slot] = __uint_as_float(f2tf32(v));
    }
    __syncthreads();

    const int w = t >> 5, lane = t & 31;
    const int mw = w & 3, nw = w >> 2;

    float acc[2][NCW][4];
    #pragma unroll
    for (int i = 0; i < 2; i++)
        #pragma unroll
        for (int j = 0; j < NCW; j++)
            #pragma unroll
            for (int q = 0; q < 4; q++) acc[i][j][q] = 0.f;

    #pragma unroll
    for (int ks = 0; ks < KS; ks++) {
        uint32_t a0[4], a1[4];
        *(float4*)a0 = *(const float4*)(As + ((((2 * mw + 0) * KS + ks) * 32 + lane) << 2));
        *(float4*)a1 = *(const float4*)(As + ((((2 * mw + 1) * KS + ks) * 32 + lane) << 2));
        #pragma unroll
        for (int nc = 0; nc < NCW; nc++) {
            uint32_t b[2];
            *(float2*)b = *(const float2*)(Bs + (((ks * NC + nw * NCW + nc) * 32 + lane) << 1));
            mma_tf32(acc[0][nc], a0, b);
            mma_tf32(acc[1][nc], a1, b);
        }
    }

    const int cbase = nw * (NCW * 8) + (lane & 3) * 2;
    #pragma unroll
    for (int mi = 0; mi < 2; mi++) {
        int r0r = row0 + (2 * mw + mi) * 16 + (lane >> 2);
        int r1r = r0r + 8;
        #pragma unroll
        for (int nc = 0; nc < NCW; nc++) {
            int cc = cbase + nc * 8;
            float2 lo = make_float2(acc[mi][nc][0], acc[mi][nc][1]);
            float2 hi = make_float2(acc[mi][nc][2], acc[mi][nc][3]);
            if (BR) {
                float2 bb = *(const float2*)(bias + cc);
                lo.x = fmaxf(lo.x + bb.x, 0.f); lo.y = fmaxf(lo.y + bb.y, 0.f);
                hi.x = fmaxf(hi.x + bb.x, 0.f); hi.y = fmaxf(hi.y + bb.y, 0.f);
            }
            if (r0r < N) *(float2*)(C + (long)r0r * FOUT + cc) = lo;
            if (r1r < N) *(float2*)(C + (long)r1r * FOUT + cc) = hi;
        }
    }
}

// ---------------- launch ----------------
static inline long cdiv(long a, long b) { return (a + b - 1) / b; }

extern "C" void kernel_launch(void* const* d_in, const int* in_sizes, int n_in,
                              void* d_out, int out_size) {
    const float* x = (const float*)d_in[0];
    const void* ei = d_in[1];
    const void* mei = d_in[2];
    const float* W1 = (const float*)d_in[3];
    const float* b1 = (const float*)d_in[4];
    const float* W2 = (const float*)d_in[5];
    const float* b2 = (const float*)d_in[6];
    const long nE = in_sizes[1] / 2;
    const long nM = in_sizes[2] / 2;
    const int n = in_sizes[0] / 64;
    float* out = (float*)d_out;

    float *bufA, *bufB, *bufC, *bufD, *dinvb, *dinvm;
    int *degb, *degm, *rowb, *rowm;
    int2 *csrb, *csrm;
    cudaGetSymbolAddress((void**)&bufA, d_bufA);
    cudaGetSymbolAddress((void**)&bufB, d_bufB);
    cudaGetSymbolAddress((void**)&bufC, d_bufC);
    cudaGetSymbolAddress((void**)&bufD, d_bufD);
    cudaGetSymbolAddress((void**)&degb, d_degb);
    cudaGetSymbolAddress((void**)&degm, d_degm);
    cudaGetSymbolAddress((void**)&dinvb, d_dinvb);
    cudaGetSymbolAddress((void**)&dinvm, d_dinvm);
    cudaGetSymbolAddress((void**)&rowb, d_rowb);
    cudaGetSymbolAddress((void**)&rowm, d_rowm);
    cudaGetSymbolAddress((void**)&csrb, d_csrb);
    cudaGetSymbolAddress((void**)&csrm, d_csrm);

    const int SM1 = (8 * 8 * 128 + 8 * 16 * 64) * 4;     // 64 KB
    const int SM2 = (8 * 16 * 128 + 16 * 8 * 64) * 4;    // 96 KB
    cudaFuncSetAttribute(mma_gemm_kernel<64, 128, true>,
                         cudaFuncAttributeMaxDynamicSharedMemorySize, SM1);
    cudaFuncSetAttribute(mma_gemm_kernel<128, 64, false>,
                         cudaFuncAttributeMaxDynamicSharedMemorySize, SM2);

    const long gemB = cdiv(n, 128);
    const long aggB = cdiv(n, 8);

    // ---- CSR build ----
    prep_kernel<<<cdiv(n, 256), 256>>>(ei, degb, degm, n);                           // 0
    count_both_kernel<<<cdiv(nE + nM, 256), 256>>>(ei, nE, degb, mei, nM, degm);     // 1
    dinv_s1_kernel<<<2 * NB, 256>>>(degb, degm, dinvb, dinvm, n);                    // 2
    scan_bs_kernel<<<1, 512>>>();                                                    // 3
    rowptr_kernel<<<2 * NB, 256>>>(degb, degm, n);                                   // 4
    scatter_both_kernel<<<cdiv(nE + nM, 256), 256>>>(ei, nE, dinvb, mei, nM, dinvm); // 5

    // ---- base graph: conv1 + conv2 ----
    agg_csr_kernel<false, false><<<aggB, 256>>>(x, bufA, rowb, degb, csrb, nullptr, n);   // 6
    mma_gemm_kernel<64, 128, true><<<gemB, 256, SM1>>>(bufA, W1, b1, bufB, n);            // 7
    mma_gemm_kernel<128, 64, false><<<gemB, 256, SM2>>>(bufB, W2, nullptr, bufC, n);      // 8
    agg_csr_kernel<true, false><<<aggB, 256>>>(bufC, bufD, rowb, degb, csrb, b2, n);      // 9

    // ---- meta graph: conv3 + conv4 + fused log_softmax ----
    agg_csr_kernel<false, false><<<aggB, 256>>>(bufD, bufA, rowm, degm, csrm, nullptr, n); // 10
    mma_gemm_kernel<64, 128, true><<<gemB, 256, SM1>>>(bufA, W1, b1, bufB, n);            // 11
    mma_gemm_kernel<128, 64, false><<<gemB, 256, SM2>>>(bufB, W2, nullptr, bufC, n);      // 12
    agg_csr_kernel<true, true><<<aggB, 256>>>(bufC, out, rowm, degm, csrm, b2, n);        // 13
}